// round 8
// baseline (speedup 1.0000x reference)
#include <cuda_runtime.h>

// Problem constants
#define NTOT   12
#define DIM    4096          // 2^NTOT
#define LAYERS 4
#define NT     256           // threads per CTA
#define NLOC   16            // amplitudes per thread per sample (DIM / NT)
#define NBATCH 1024
#define SROW   18            // padded ull row stride (R5-proven conflict-free)
#define BUF_ULL (NT * SROW)  // 4608 ull per sample buffer
#define DYN_SMEM (2 * BUF_ULL * 8)   // 73728 bytes (two sample buffers)

typedef unsigned long long ull;

// ---- packed f32x2 primitives (ptxas will not emit FFMA2 from C++) ----------
__device__ __forceinline__ ull pk(float lo, float hi) {
    ull r; asm("mov.b64 %0,{%1,%2};" : "=l"(r) : "f"(lo), "f"(hi)); return r;
}
__device__ __forceinline__ void upk(ull v, float& lo, float& hi) {
    asm("mov.b64 {%0,%1},%2;" : "=f"(lo), "=f"(hi) : "l"(v));
}
__device__ __forceinline__ ull swp(ull v) {   // (re,im) -> (im,re)
    ull r;
    asm("{\n\t.reg .b32 lo,hi;\n\tmov.b64 {lo,hi},%1;\n\tmov.b64 %0,{hi,lo};\n\t}"
        : "=l"(r) : "l"(v));
    return r;
}
__device__ __forceinline__ ull ffma2(ull a, ull b, ull c) {
    ull d; asm("fma.rn.f32x2 %0,%1,%2,%3;" : "=l"(d) : "l"(a), "l"(b), "l"(c)); return d;
}
__device__ __forceinline__ ull fmul2(ull a, ull b) {
    ull d; asm("mul.rn.f32x2 %0,%1,%2;" : "=l"(d) : "l"(a), "l"(b)); return d;
}

// 2x2 complex gate on local bit BBIT of BOTH samples' 16 packed amplitudes.
// Coefficients loaded once (shared circuit); butterflies interleaved -> 2x ILP.
template <int BBIT>
__device__ __forceinline__ void gate_packed2(ull* va, ull* vb, const ull* __restrict__ C) {
    const ulonglong2* C2 = reinterpret_cast<const ulonglong2*>(C);
    ulonglong2 p0 = C2[0], p1 = C2[1], p2 = C2[2], p3 = C2[3];
    const ull c00r = p0.x, c00x = p0.y, c01r = p1.x, c01x = p1.y;
    const ull c10r = p2.x, c10x = p2.y, c11r = p3.x, c11x = p3.y;
#pragma unroll
    for (int j = 0; j < NLOC; j++) {
        if (j & (1 << BBIT)) continue;
        const int k = j | (1 << BBIT);
        {
            ull x = va[j], y = va[k];
            ull sx = swp(x), sy = swp(y);
            va[j] = ffma2(c00r, x, ffma2(c00x, sx, ffma2(c01r, y, fmul2(c01x, sy))));
            va[k] = ffma2(c10r, x, ffma2(c10x, sx, ffma2(c11r, y, fmul2(c11x, sy))));
        }
        {
            ull x = vb[j], y = vb[k];
            ull sx = swp(x), sy = swp(y);
            vb[j] = ffma2(c00r, x, ffma2(c00x, sx, ffma2(c01r, y, fmul2(c01x, sy))));
            vb[k] = ffma2(c10r, x, ffma2(c10x, sx, ffma2(c11r, y, fmul2(c11x, sy))));
        }
    }
}

// Index maps (global amplitude index from (thread t, local slot j)):
//   mapping A: idx = (t<<4) | j                       -> local = idx[3:0]  (qubits 8..11)
//   mapping B: idx = ((t>>4)<<8) | (j<<4) | (t&15)    -> local = idx[7:4]  (qubits 4..7)
//   mapping C: idx = (j<<8) | t                       -> local = idx[11:8] (qubits 0..3)
//
// Zigzag walk L0:A,B,C / L1:C,B,A (x2). Exchange layouts are the R5-proven
// stride-18 patterns (bank-audited conflict-free):
//   warp-local A<->B: store row=16*h4+j, col=l4;  load LDS.128 row=t.
//   cross B<->C:      store row=j*16+l4, col=h4^l4; load row=t, off=j^l4.
// Both samples perform identical exchanges in disjoint buffers; each
// __syncthreads / __syncwarp serves BOTH samples (per-sample sync cost halved),
// and one sample's gates overlap the other's LDS latency.

__global__ __launch_bounds__(NT, 2)
void qddpm_kernel(const float* __restrict__ gre, const float* __restrict__ gim,
                  const float* __restrict__ params,
                  const float* __restrict__ uvec, float2* __restrict__ out) {
    extern __shared__ __align__(16) ull dsm[];
    ull* bufA = dsm;              // sample 0 exchange buffer
    ull* bufB = dsm + BUF_ULL;    // sample 1 exchange buffer
    __shared__ __align__(16) ull sG[LAYERS * NTOT * 8];   // packed gate coeffs
    __shared__ float sb0[16], sb1[16];

    const int t = threadIdx.x;
    const int s0 = 2 * blockIdx.x;        // this CTA's two samples
    const int s1 = s0 + 1;
    const int l4 = t & 15;
    const int h4 = t >> 4;

    const float u0 = __ldg(uvec + s0);
    const float u1 = __ldg(uvec + s1);

    // ---- in-CTA gate prep: fused U = Ry(t2)*Rx(t1), stored as f32x2 packs ----
    if (t < LAYERS * NTOT) {
        int lay = t / NTOT;
        int q   = t - lay * NTOT;
        float t1 = params[2 * NTOT * lay + q]        * 0.5f;
        float t2 = params[2 * NTOT * lay + NTOT + q] * 0.5f;
        float s1f, c1, s2, c2;
        sincosf(t1, &s1f, &c1);
        sincosf(t2, &s2, &c2);
        float u00r =  c2 * c1, u00i =  s2 * s1f;
        float u01r = -s2 * c1, u01i = -c2 * s1f;
        float u10r =  s2 * c1, u10i = -c2 * s1f;
        float u11r =  c2 * c1, u11i = -s2 * s1f;
        ull* G = &sG[t * 8];
        G[0] = pk(u00r,  u00r);  G[1] = pk(-u00i, u00i);
        G[2] = pk(u01r,  u01r);  G[3] = pk(-u01i, u01i);
        G[4] = pk(u10r,  u10r);  G[5] = pk(-u10i, u10i);
        G[6] = pk(u11r,  u11r);  G[7] = pk(-u11i, u11i);
    }

    // ---- load both states, mapping A: thread t holds idx = t*16 + j ----
    ull va[NLOC], vb[NLOC];
    {
        const float4* pr = reinterpret_cast<const float4*>(gre + (size_t)s0 * DIM + t * NLOC);
        const float4* pi = reinterpret_cast<const float4*>(gim + (size_t)s0 * DIM + t * NLOC);
        const float4* qr = reinterpret_cast<const float4*>(gre + (size_t)s1 * DIM + t * NLOC);
        const float4* qi = reinterpret_cast<const float4*>(gim + (size_t)s1 * DIM + t * NLOC);
#pragma unroll
        for (int w = 0; w < 4; w++) {
            float4 f = pr[w], g = pi[w];
            va[4*w+0] = pk(f.x, g.x); va[4*w+1] = pk(f.y, g.y);
            va[4*w+2] = pk(f.z, g.z); va[4*w+3] = pk(f.w, g.w);
            float4 f2 = qr[w], g2 = qi[w];
            vb[4*w+0] = pk(f2.x, g2.x); vb[4*w+1] = pk(f2.y, g2.y);
            vb[4*w+2] = pk(f2.z, g2.z); vb[4*w+3] = pk(f2.w, g2.w);
        }
    }
    const ull SGN = 0x8000000080000000ULL;   // packed sign-bit flip
    __syncthreads();  // sG ready

#pragma unroll 1
    for (int sl = 0; sl < 2; ++sl) {
        const ull* G0 = sG + (2 * sl)     * NTOT * 8;  // even layer: A,B,C
        const ull* G1 = sG + (2 * sl + 1) * NTOT * 8;  // odd  layer: C,B,A

        // ======== even layer: gates A ========
        gate_packed2<3>(va, vb, G0 + 8 * 8);
        gate_packed2<2>(va, vb, G0 + 9 * 8);
        gate_packed2<1>(va, vb, G0 + 10 * 8);
        gate_packed2<0>(va, vb, G0 + 11 * 8);

        // E1: A -> B  (warp-local, both buffers)
        __syncwarp();
        { ull* sa = bufA + h4 * (16 * SROW) + l4;
          ull* sb = bufB + h4 * (16 * SROW) + l4;
#pragma unroll
          for (int j = 0; j < NLOC; j++) { sa[j * SROW] = va[j]; sb[j * SROW] = vb[j]; } }
        __syncwarp();
        { const ulonglong2* la = reinterpret_cast<const ulonglong2*>(bufA + t * SROW);
          const ulonglong2* lb = reinterpret_cast<const ulonglong2*>(bufB + t * SROW);
#pragma unroll
          for (int m = 0; m < 8; m++) {
              ulonglong2 w1 = la[m]; va[2*m] = w1.x; va[2*m+1] = w1.y;
              ulonglong2 w2 = lb[m]; vb[2*m] = w2.x; vb[2*m+1] = w2.y;
          } }

        // gates B
        gate_packed2<3>(va, vb, G0 + 4 * 8);
        gate_packed2<2>(va, vb, G0 + 5 * 8);
        gate_packed2<1>(va, vb, G0 + 6 * 8);
        gate_packed2<0>(va, vb, G0 + 7 * 8);

        // E2: B -> C  (cross-warp, XOR swizzle; shared barriers)
        __syncthreads();
        { ull* sa = bufA + l4 * SROW + (h4 ^ l4);
          ull* sb = bufB + l4 * SROW + (h4 ^ l4);
#pragma unroll
          for (int j = 0; j < NLOC; j++) { sa[j * (16*SROW)] = va[j]; sb[j * (16*SROW)] = vb[j]; } }
        __syncthreads();
        { const ull* la = bufA + t * SROW;
          const ull* lb = bufB + t * SROW;
#pragma unroll
          for (int j = 0; j < NLOC; j++) { va[j] = la[j ^ l4]; vb[j] = lb[j ^ l4]; } }

        // gates C + CZ(C)
        gate_packed2<3>(va, vb, G0 + 0 * 8);
        gate_packed2<2>(va, vb, G0 + 1 * 8);
        gate_packed2<1>(va, vb, G0 + 2 * 8);
        gate_packed2<0>(va, vb, G0 + 3 * 8);
#pragma unroll
        for (int j = 0; j < NLOC; j++) {
            int idx = (j << 8) | t;
            if (__popc(idx & (idx >> 1)) & 1) { va[j] ^= SGN; vb[j] ^= SGN; }
        }

        // ======== odd layer: gates C ========
        gate_packed2<3>(va, vb, G1 + 0 * 8);
        gate_packed2<2>(va, vb, G1 + 1 * 8);
        gate_packed2<1>(va, vb, G1 + 2 * 8);
        gate_packed2<0>(va, vb, G1 + 3 * 8);

        // E3: C -> B  (cross-warp, same involution code)
        __syncthreads();
        { ull* sa = bufA + l4 * SROW + (h4 ^ l4);
          ull* sb = bufB + l4 * SROW + (h4 ^ l4);
#pragma unroll
          for (int j = 0; j < NLOC; j++) { sa[j * (16*SROW)] = va[j]; sb[j * (16*SROW)] = vb[j]; } }
        __syncthreads();
        { const ull* la = bufA + t * SROW;
          const ull* lb = bufB + t * SROW;
#pragma unroll
          for (int j = 0; j < NLOC; j++) { va[j] = la[j ^ l4]; vb[j] = lb[j ^ l4]; } }

        // gates B
        gate_packed2<3>(va, vb, G1 + 4 * 8);
        gate_packed2<2>(va, vb, G1 + 5 * 8);
        gate_packed2<1>(va, vb, G1 + 6 * 8);
        gate_packed2<0>(va, vb, G1 + 7 * 8);

        // E4: B -> A  (warp-local)
        __syncwarp();
        { ull* sa = bufA + h4 * (16 * SROW) + l4;
          ull* sb = bufB + h4 * (16 * SROW) + l4;
#pragma unroll
          for (int j = 0; j < NLOC; j++) { sa[j * SROW] = va[j]; sb[j * SROW] = vb[j]; } }
        __syncwarp();
        { const ulonglong2* la = reinterpret_cast<const ulonglong2*>(bufA + t * SROW);
          const ulonglong2* lb = reinterpret_cast<const ulonglong2*>(bufB + t * SROW);
#pragma unroll
          for (int m = 0; m < 8; m++) {
              ulonglong2 w1 = la[m]; va[2*m] = w1.x; va[2*m+1] = w1.y;
              ulonglong2 w2 = lb[m]; vb[2*m] = w2.x; vb[2*m+1] = w2.y;
          } }

        // gates A + CZ(A)
        gate_packed2<3>(va, vb, G1 + 8 * 8);
        gate_packed2<2>(va, vb, G1 + 9 * 8);
        gate_packed2<1>(va, vb, G1 + 10 * 8);
        gate_packed2<0>(va, vb, G1 + 11 * 8);
#pragma unroll
        for (int j = 0; j < NLOC; j++) {
            int idx = (t << 4) | j;
            if (__popc(idx & (idx >> 1)) & 1) { va[j] ^= SGN; vb[j] ^= SGN; }
        }
    }

    // ---- Sampling in mapping A (both samples): thread t's 16 amps share
    //      ancilla m = h4; collapsed index k = (l4<<4)|j. ----
    float p0, p1;
    {
        ull acc0 = 0, acc1 = 0;
#pragma unroll
        for (int j = 0; j < NLOC; j++) {
            acc0 = ffma2(va[j], va[j], acc0);
            acc1 = ffma2(vb[j], vb[j], acc1);
        }
        float a, c;
        upk(acc0, a, c); p0 = a + c;
        upk(acc1, a, c); p1 = a + c;
    }
#pragma unroll
    for (int m = 1; m < 16; m <<= 1) {
        p0 += __shfl_xor_sync(0xffffffffu, p0, m);
        p1 += __shfl_xor_sync(0xffffffffu, p1, m);
    }
    if (l4 == 0) { sb0[h4] = p0; sb1[h4] = p1; }
    __syncthreads();

    int mm0, mm1;
    float nn0, nn1;
    {
        float cdf = 0.f, cdfs[16];
#pragma unroll
        for (int j = 0; j < 16; j++) { cdf += sb0[j]; cdfs[j] = cdf; }
        float th = u0 * cdf;
        int m = 0; bool found = false;
#pragma unroll
        for (int j = 0; j < 16; j++) if (!found && cdfs[j] >= th) { m = j; found = true; }
        mm0 = m; nn0 = rsqrtf(sb0[m]);
    }
    {
        float cdf = 0.f, cdfs[16];
#pragma unroll
        for (int j = 0; j < 16; j++) { cdf += sb1[j]; cdfs[j] = cdf; }
        float th = u1 * cdf;
        int m = 0; bool found = false;
#pragma unroll
        for (int j = 0; j < 16; j++) if (!found && cdfs[j] >= th) { m = j; found = true; }
        mm1 = m; nn1 = rsqrtf(sb1[m]);
    }

    if (h4 == mm0) {   // half-warp writes sample s0's 256 float2 contiguously
        ull nn2 = pk(nn0, nn0);
        ulonglong2* po = reinterpret_cast<ulonglong2*>(out + (size_t)s0 * 256 + l4 * 16);
#pragma unroll
        for (int m2 = 0; m2 < 8; m2++) {
            ulonglong2 w;
            w.x = fmul2(va[2*m2],   nn2);
            w.y = fmul2(va[2*m2+1], nn2);
            po[m2] = w;
        }
    }
    if (h4 == mm1) {
        ull nn2 = pk(nn1, nn1);
        ulonglong2* po = reinterpret_cast<ulonglong2*>(out + (size_t)s1 * 256 + l4 * 16);
#pragma unroll
        for (int m2 = 0; m2 < 8; m2++) {
            ulonglong2 w;
            w.x = fmul2(vb[2*m2],   nn2);
            w.y = fmul2(vb[2*m2+1], nn2);
            po[m2] = w;
        }
    }
}

// ---------------------------------------------------------------------------
// inputs: d_in[0]=inputs_re [B,DIM] f32, d_in[1]=inputs_im [B,DIM] f32,
//         d_in[2]=params [96] f32,  d_in[3]=u [B] f32
// output: [B, 256, 2] f32
// ---------------------------------------------------------------------------
extern "C" void kernel_launch(void* const* d_in, const int* in_sizes, int n_in,
                              void* d_out, int out_size) {
    (void)in_sizes; (void)n_in; (void)out_size;
    const float* gre    = (const float*)d_in[0];
    const float* gim    = (const float*)d_in[1];
    const float* params = (const float*)d_in[2];
    const float* uvec   = (const float*)d_in[3];
    float2* out = (float2*)d_out;

    static int configured = 0;
    if (!configured) {
        cudaFuncSetAttribute(qddpm_kernel,
                             cudaFuncAttributeMaxDynamicSharedMemorySize, DYN_SMEM);
        configured = 1;
    }
    qddpm_kernel<<<NBATCH / 2, NT, DYN_SMEM>>>(gre, gim, params, uvec, out);
}

// round 9
// speedup vs baseline: 1.1184x; 1.1184x over previous
#include <cuda_runtime.h>

// Problem constants
#define NTOT   12
#define DIM    4096          // 2^NTOT
#define LAYERS 4
#define NT     256           // threads per CTA
#define NLOC   16            // amplitudes per thread (DIM / NT)
#define NBATCH 1024
#define SROW   18            // padded ull row stride for exchange buffer
#define NSM    148           // GB300 per-die... sm_103a active SMs (CTA trio = bid, bid+148, bid+296)
#define STAGGER_CYC 1500     // ~1/3 of the measured inter-barrier interval

typedef unsigned long long ull;

// ---- packed f32x2 primitives (ptxas will not emit FFMA2 from C++) ----------
__device__ __forceinline__ ull pk(float lo, float hi) {
    ull r; asm("mov.b64 %0,{%1,%2};" : "=l"(r) : "f"(lo), "f"(hi)); return r;
}
__device__ __forceinline__ void upk(ull v, float& lo, float& hi) {
    asm("mov.b64 {%0,%1},%2;" : "=f"(lo), "=f"(hi) : "l"(v));
}
__device__ __forceinline__ ull swp(ull v) {   // (re,im) -> (im,re)
    ull r;
    asm("{\n\t.reg .b32 lo,hi;\n\tmov.b64 {lo,hi},%1;\n\tmov.b64 %0,{hi,lo};\n\t}"
        : "=l"(r) : "l"(v));
    return r;
}
__device__ __forceinline__ ull ffma2(ull a, ull b, ull c) {
    ull d; asm("fma.rn.f32x2 %0,%1,%2,%3;" : "=l"(d) : "l"(a), "l"(b), "l"(c)); return d;
}
__device__ __forceinline__ ull fmul2(ull a, ull b) {
    ull d; asm("mul.rn.f32x2 %0,%1,%2;" : "=l"(d) : "l"(a), "l"(b)); return d;
}
__device__ __forceinline__ long long rdclk() {
    long long c; asm volatile("mov.s64 %0, %%clock64;" : "=l"(c)); return c;
}

// Apply a 2x2 complex gate on local bit BBIT of 16 packed (re,im) amplitudes.
// Coeff packs: C[0]=(u00r,u00r) C[1]=(-u00i,u00i) C[2]=(u01r,u01r) C[3]=(-u01i,u01i)
//              C[4..7] row 1.
template <int BBIT>
__device__ __forceinline__ void gate_packed(ull* v, const ull* __restrict__ C) {
    const ulonglong2* C2 = reinterpret_cast<const ulonglong2*>(C);
    ulonglong2 p0 = C2[0], p1 = C2[1], p2 = C2[2], p3 = C2[3];
    const ull c00r = p0.x, c00x = p0.y, c01r = p1.x, c01x = p1.y;
    const ull c10r = p2.x, c10x = p2.y, c11r = p3.x, c11x = p3.y;
#pragma unroll
    for (int j = 0; j < NLOC; j++) {
        if (j & (1 << BBIT)) continue;
        const int k = j | (1 << BBIT);
        ull x = v[j], y = v[k];
        ull sx = swp(x), sy = swp(y);
        v[j] = ffma2(c00r, x, ffma2(c00x, sx, ffma2(c01r, y, fmul2(c01x, sy))));
        v[k] = ffma2(c10r, x, ffma2(c10x, sx, ffma2(c11r, y, fmul2(c11x, sy))));
    }
}

// Index maps (global amplitude index from (thread t, local slot j)):
//   mapping A: idx = (t<<4) | j                       -> local = idx[3:0]  (qubits 8..11)
//   mapping B: idx = ((t>>4)<<8) | (j<<4) | (t&15)    -> local = idx[7:4]  (qubits 4..7)
//   mapping C: idx = (j<<8) | t                       -> local = idx[11:8] (qubits 0..3)
//
// Zigzag walk L0:A,B,C / L1:C,B,A / L2:A,B,C / L3:C,B,A.  A<->B warp-local
// (16-thread groups); B<->C cross-warp with XOR-on-low-nibble swizzle
// (bank-audited conflict-free).  All layouts identical to the proven R5 kernel;
// the ONLY change this round is the co-resident-CTA phase stagger below.

__global__ __launch_bounds__(NT, 3)
void qddpm_kernel(const float* __restrict__ gre, const float* __restrict__ gim,
                  const float* __restrict__ params,
                  const float* __restrict__ uvec, float2* __restrict__ out) {
    __shared__ __align__(16) ull sbuf[NT * SROW];      // 36864 B exchange buffer
    __shared__ __align__(16) ull sG[LAYERS * NTOT * 8];// 3072 B packed gate coeffs
    __shared__ float sbins[16];

    const int t = threadIdx.x;
    const int b = blockIdx.x;
    const int l4 = t & 15;          // low nibble of thread id
    const int h4 = t >> 4;          // high nibble

    // ---- co-resident CTA phase stagger -----------------------------------
    // Initial wave puts CTAs b, b+148, b+296 on the same SM at t=0 running
    // identical code -> phase-locked barriers -> fma pipe idles during every
    // exchange. Offset slots 1 and 2 by 1/3 and 2/3 of the inter-barrier
    // interval so the trio's compute and exchange phases interleave. Later
    // CTAs arrive via work-steal (already staggered) and are not delayed.
    {
        int w = b / NSM;             // initial-wave slot (0,1,2) or later (>2)
        if (w == 1 || w == 2) {
            long long tgt = rdclk() + (long long)(w * STAGGER_CYC);
            while (rdclk() < tgt) { }
        }
    }

    // ---- in-CTA gate prep: fused U = Ry(t2)*Rx(t1), stored as f32x2 packs ----
    if (t < LAYERS * NTOT) {
        int lay = t / NTOT;
        int q   = t - lay * NTOT;
        float t1 = params[2 * NTOT * lay + q]        * 0.5f;
        float t2 = params[2 * NTOT * lay + NTOT + q] * 0.5f;
        float s1, c1, s2, c2;
        sincosf(t1, &s1, &c1);
        sincosf(t2, &s2, &c2);
        float u00r =  c2 * c1, u00i =  s2 * s1;
        float u01r = -s2 * c1, u01i = -c2 * s1;
        float u10r =  s2 * c1, u10i = -c2 * s1;
        float u11r =  c2 * c1, u11i = -s2 * s1;
        ull* G = &sG[t * 8];
        G[0] = pk(u00r,  u00r);  G[1] = pk(-u00i, u00i);
        G[2] = pk(u01r,  u01r);  G[3] = pk(-u01i, u01i);
        G[4] = pk(u10r,  u10r);  G[5] = pk(-u10i, u10i);
        G[6] = pk(u11r,  u11r);  G[7] = pk(-u11i, u11i);
    }

    // ---- load state, mapping A: thread t holds idx = t*16 + j; pack (re,im) ----
    ull v[NLOC];
    {
        const float4* pr = reinterpret_cast<const float4*>(gre + (size_t)b * DIM + t * NLOC);
        const float4* pi = reinterpret_cast<const float4*>(gim + (size_t)b * DIM + t * NLOC);
#pragma unroll
        for (int w = 0; w < 4; w++) {
            float4 f = pr[w];
            float4 g = pi[w];
            v[4 * w + 0] = pk(f.x, g.x);
            v[4 * w + 1] = pk(f.y, g.y);
            v[4 * w + 2] = pk(f.z, g.z);
            v[4 * w + 3] = pk(f.w, g.w);
        }
    }
    const ull SGN = 0x8000000080000000ULL;   // packed sign-bit flip
    __syncthreads();  // sG ready

#pragma unroll 1
    for (int sl = 0; sl < 2; ++sl) {
        const ull* G0 = sG + (2 * sl)     * NTOT * 8;  // even layer: A,B,C
        const ull* G1 = sG + (2 * sl + 1) * NTOT * 8;  // odd  layer: C,B,A

        // ======== even layer: gates A ========
        gate_packed<3>(v, G0 + 8 * 8);
        gate_packed<2>(v, G0 + 9 * 8);
        gate_packed<1>(v, G0 + 10 * 8);
        gate_packed<0>(v, G0 + 11 * 8);

        // E1: A -> B  (warp-local)
        __syncwarp();
        { ull* st = sbuf + h4 * (16 * SROW) + l4;
#pragma unroll
          for (int j = 0; j < NLOC; j++) st[j * SROW] = v[j]; }
        __syncwarp();
        { const ulonglong2* ld = reinterpret_cast<const ulonglong2*>(sbuf + t * SROW);
#pragma unroll
          for (int m = 0; m < 8; m++) { ulonglong2 w = ld[m]; v[2*m] = w.x; v[2*m+1] = w.y; } }

        // gates B
        gate_packed<3>(v, G0 + 4 * 8);
        gate_packed<2>(v, G0 + 5 * 8);
        gate_packed<1>(v, G0 + 6 * 8);
        gate_packed<0>(v, G0 + 7 * 8);

        // E2: B -> C  (cross-warp, XOR swizzle)
        __syncthreads();
        { ull* st = sbuf + l4 * SROW + (h4 ^ l4);
#pragma unroll
          for (int j = 0; j < NLOC; j++) st[j * (16 * SROW)] = v[j]; }
        __syncthreads();
        { const ull* ld = sbuf + t * SROW;
#pragma unroll
          for (int j = 0; j < NLOC; j++) v[j] = ld[j ^ l4]; }

        // gates C + CZ(C)
        gate_packed<3>(v, G0 + 0 * 8);
        gate_packed<2>(v, G0 + 1 * 8);
        gate_packed<1>(v, G0 + 2 * 8);
        gate_packed<0>(v, G0 + 3 * 8);
#pragma unroll
        for (int j = 0; j < NLOC; j++) {
            int idx = (j << 8) | t;
            if (__popc(idx & (idx >> 1)) & 1) v[j] ^= SGN;
        }

        // ======== odd layer: gates C ========
        gate_packed<3>(v, G1 + 0 * 8);
        gate_packed<2>(v, G1 + 1 * 8);
        gate_packed<1>(v, G1 + 2 * 8);
        gate_packed<0>(v, G1 + 3 * 8);

        // E3: C -> B  (cross-warp, involution: same code as E2)
        __syncthreads();
        { ull* st = sbuf + l4 * SROW + (h4 ^ l4);
#pragma unroll
          for (int j = 0; j < NLOC; j++) st[j * (16 * SROW)] = v[j]; }
        __syncthreads();
        { const ull* ld = sbuf + t * SROW;
#pragma unroll
          for (int j = 0; j < NLOC; j++) v[j] = ld[j ^ l4]; }

        // gates B
        gate_packed<3>(v, G1 + 4 * 8);
        gate_packed<2>(v, G1 + 5 * 8);
        gate_packed<1>(v, G1 + 6 * 8);
        gate_packed<0>(v, G1 + 7 * 8);

        // E4: B -> A  (warp-local, involution of E1)
        __syncwarp();
        { ull* st = sbuf + h4 * (16 * SROW) + l4;
#pragma unroll
          for (int j = 0; j < NLOC; j++) st[j * SROW] = v[j]; }
        __syncwarp();
        { const ulonglong2* ld = reinterpret_cast<const ulonglong2*>(sbuf + t * SROW);
#pragma unroll
          for (int m = 0; m < 8; m++) { ulonglong2 w = ld[m]; v[2*m] = w.x; v[2*m+1] = w.y; } }

        // gates A + CZ(A)
        gate_packed<3>(v, G1 + 8 * 8);
        gate_packed<2>(v, G1 + 9 * 8);
        gate_packed<1>(v, G1 + 10 * 8);
        gate_packed<0>(v, G1 + 11 * 8);
#pragma unroll
        for (int j = 0; j < NLOC; j++) {
            int idx = (t << 4) | j;
            if (__popc(idx & (idx >> 1)) & 1) v[j] ^= SGN;
        }
    }

    // ---- Sampling in mapping A: thread t's 16 amps share ancilla m = h4;
    //      collapsed index k = (l4<<4)|j.  probs via 16-lane shfl reduction. ----
    float p;
    {
        ull acc = 0;
#pragma unroll
        for (int j = 0; j < NLOC; j++) acc = ffma2(v[j], v[j], acc);
        float a, c; upk(acc, a, c);
        p = a + c;
    }
#pragma unroll
    for (int m = 1; m < 16; m <<= 1)
        p += __shfl_xor_sync(0xffffffffu, p, m);
    if (l4 == 0) sbins[h4] = p;
    __syncthreads();

    int   mm;
    float nn;
    {
        float cdfs[16];
        float cdf = 0.f;
#pragma unroll
        for (int j = 0; j < 16; j++) { cdf += sbins[j]; cdfs[j] = cdf; }
        float thresh = __ldg(uvec + b) * cdf;  // inverse-CDF multinomial
        int m = 0; bool found = false;
#pragma unroll
        for (int j = 0; j < 16; j++) {
            if (!found && cdfs[j] >= thresh) { m = j; found = true; }
        }
        mm = m;
        nn = rsqrtf(sbins[m]);
    }

    if (h4 == mm) {   // half-warp writes 256 float2 contiguously, 16B stores
        ull nn2 = pk(nn, nn);
        ulonglong2* po = reinterpret_cast<ulonglong2*>(out + (size_t)b * 256 + l4 * 16);
#pragma unroll
        for (int m2 = 0; m2 < 8; m2++) {
            ulonglong2 w;
            w.x = fmul2(v[2 * m2],     nn2);
            w.y = fmul2(v[2 * m2 + 1], nn2);
            po[m2] = w;
        }
    }
}

// ---------------------------------------------------------------------------
// inputs: d_in[0]=inputs_re [B,DIM] f32, d_in[1]=inputs_im [B,DIM] f32,
//         d_in[2]=params [96] f32,  d_in[3]=u [B] f32
// output: [B, 256, 2] f32
// ---------------------------------------------------------------------------
extern "C" void kernel_launch(void* const* d_in, const int* in_sizes, int n_in,
                              void* d_out, int out_size) {
    (void)in_sizes; (void)n_in; (void)out_size;
    const float* gre    = (const float*)d_in[0];
    const float* gim    = (const float*)d_in[1];
    const float* params = (const float*)d_in[2];
    const float* uvec   = (const float*)d_in[3];
    float2* out = (float2*)d_out;

    qddpm_kernel<<<NBATCH, NT>>>(gre, gim, params, uvec, out);
}